// round 17
// baseline (speedup 1.0000x reference)
#include <cuda_runtime.h>
#include <limits.h>

#define BB 8
#define NN 8192
#define MM 2048
#define CC 64
#define KK 64
#define R2 0.01f
#define NZC 40             // z cells (cell_z = 0.025); xy stays 10x10 (0.1)
#define NCELL (100 * NZC)  // 4000 cells per batch
#define RREACH 0.1002f     // conservative cell reach (covers d2 rounding slack)
#define HCAP 128           // per-query candidate-hit cap (max expected ~75)
#define MAXCOL 16          // max (cx,cy) columns per query (4x4)
#define NBQBLK ((MM / 8) * BB)     // 2048 ballquery blocks
#define NTRBLK ((NN / 64) * BB)    // 1024 transpose blocks

// Scratch (no cudaMalloc allowed). 16B alignment kept defensively.
__device__ __align__(16) float  g_feat[BB * NN * 64];   // feature rows, 256B
__device__ __align__(16) float4 g_xyzw[BB * NN];        // xyz per point
__device__ __align__(16) int    g_idx[BB * MM * KK];    // neighbor indices
__device__ __align__(16) int    g_qorder[BB * MM];      // sorted query order
__device__ __align__(16) int    g_cellcnt[BB * NCELL];  // zero-init; re-zeroed
__device__ __align__(16) int    g_cellstart[BB * (NCELL + 1)];
__device__ __align__(16) int    g_cellofs[BB * NCELL];
__device__ __align__(16) float4 g_cellpts[BB * NN];     // cell-sorted points

__device__ __forceinline__ int cell_of(float x, float y, float z)
{
    int cx = (int)(x * 10.0f);         cx = min(max(cx, 0), 9);
    int cy = (int)(y * 10.0f);         cy = min(max(cy, 0), 9);
    int cz = (int)(z * (float)NZC);    cz = min(max(cz, 0), NZC - 1);
    return (cx * 10 + cy) * NZC + cz;
}

// ---------------------------------------------------------------------------
// K1: standalone cell histogram.
// ---------------------------------------------------------------------------
__global__ void __launch_bounds__(256) hist_kernel(const float* __restrict__ xyz)
{
    const int b = blockIdx.y;
    const int n = blockIdx.x * 256 + threadIdx.x;
    const float x = xyz[(b * 3 + 0) * NN + n];
    const float y = xyz[(b * 3 + 1) * NN + n];
    const float z = xyz[(b * 3 + 2) * NN + n];
    atomicAdd(&g_cellcnt[b * NCELL + cell_of(x, y, z)], 1);
}

// ---------------------------------------------------------------------------
// K1b: spatial sort of queries by coarse 10x10x10 cell. One block per batch.
// g_qorder is rewritten fully each launch; output values are order-invariant.
// ---------------------------------------------------------------------------
__global__ void __launch_bounds__(1024) qsort_kernel(const float* __restrict__ new_xyz)
{
    __shared__ int scnt[1024];
    __shared__ int sofs[1000];
    const int b   = blockIdx.x;
    const int tid = threadIdx.x;

    scnt[tid] = 0;
    __syncthreads();

    int qc[2];
    #pragma unroll
    for (int i = 0; i < 2; ++i) {
        const int m = i * 1024 + tid;
        const float x = new_xyz[(b * 3 + 0) * MM + m];
        const float y = new_xyz[(b * 3 + 1) * MM + m];
        const float z = new_xyz[(b * 3 + 2) * MM + m];
        int cx = min(max((int)(x * 10.0f), 0), 9);
        int cy = min(max((int)(y * 10.0f), 0), 9);
        int cz = min(max((int)(z * 10.0f), 0), 9);
        qc[i] = (cx * 10 + cy) * 10 + cz;
        atomicAdd(&scnt[qc[i]], 1);
    }
    __syncthreads();

    const int v = scnt[tid];
    #pragma unroll
    for (int d = 1; d < 1024; d <<= 1) {
        const int t = (tid >= d) ? scnt[tid - d] : 0;
        __syncthreads();
        scnt[tid] += t;
        __syncthreads();
    }
    if (tid < 1000) sofs[tid] = scnt[tid] - v;
    __syncthreads();

    #pragma unroll
    for (int i = 0; i < 2; ++i) {
        const int m   = i * 1024 + tid;
        const int pos = atomicAdd(&sofs[qc[i]], 1);
        g_qorder[b * MM + pos] = m;
    }
}

// ---------------------------------------------------------------------------
// K2: scan per batch over 4000 cells (int4 per thread). Re-zeros g_cellcnt.
// ---------------------------------------------------------------------------
__global__ void __launch_bounds__(1024) scan_kernel()
{
    __shared__ int s[1024];
    const int b   = blockIdx.x;
    const int tid = threadIdx.x;

    int4 v = make_int4(0, 0, 0, 0);
    if (tid < NCELL / 4) {
        v = ((int4*)(g_cellcnt + b * NCELL))[tid];
        ((int4*)(g_cellcnt + b * NCELL))[tid] = make_int4(0, 0, 0, 0);
    }
    const int tsum = v.x + v.y + v.z + v.w;
    s[tid] = tsum;
    __syncthreads();
    #pragma unroll
    for (int d = 1; d < 1024; d <<= 1) {
        const int t = (tid >= d) ? s[tid - d] : 0;
        __syncthreads();
        s[tid] += t;
        __syncthreads();
    }
    if (tid < NCELL / 4) {
        const int excl = s[tid] - tsum;
        const int cbase = 4 * tid;
        int e0 = excl;
        int e1 = excl + v.x;
        int e2 = e1 + v.y;
        int e3 = e2 + v.z;
        g_cellstart[b * (NCELL + 1) + cbase + 0] = e0;
        g_cellstart[b * (NCELL + 1) + cbase + 1] = e1;
        g_cellstart[b * (NCELL + 1) + cbase + 2] = e2;
        g_cellstart[b * (NCELL + 1) + cbase + 3] = e3;
        g_cellofs[b * NCELL + cbase + 0] = e0;
        g_cellofs[b * NCELL + cbase + 1] = e1;
        g_cellofs[b * NCELL + cbase + 2] = e2;
        g_cellofs[b * NCELL + cbase + 3] = e3;
    }
    if (tid == NCELL / 4 - 1)
        g_cellstart[b * (NCELL + 1) + NCELL] = s[tid];
}

// ---------------------------------------------------------------------------
// K3: scatter points into cell-sorted array.
// ---------------------------------------------------------------------------
__global__ void __launch_bounds__(1024) scatter_kernel(const float* __restrict__ xyz)
{
    const int b = blockIdx.y;
    const int n = blockIdx.x * 1024 + threadIdx.x;
    const float x = xyz[(b * 3 + 0) * NN + n];
    const float y = xyz[(b * 3 + 1) * NN + n];
    const float z = xyz[(b * 3 + 2) * NN + n];
    const int pos = atomicAdd(&g_cellofs[b * NCELL + cell_of(x, y, z)], 1);
    g_cellpts[b * NN + pos] = make_float4(x, y, z, __int_as_float(n));
}

// ---------------------------------------------------------------------------
// Bitonic sorts (unchanged)
// ---------------------------------------------------------------------------
__device__ __forceinline__ void cmpex(int& v, int e_lane_bits, int j, int k, int lane)
{
    const int pv = __shfl_xor_sync(0xffffffffu, v, j);
    const bool up = ((e_lane_bits & k) == 0);
    const bool lo = ((lane & j) == 0);
    v = ((lo == up) ? min(v, pv) : max(v, pv));
}

__device__ __forceinline__ void bitonic64(int& v0, int& v1, int lane)
{
    #pragma unroll
    for (int k = 2; k <= 64; k <<= 1) {
        #pragma unroll
        for (int j = k >> 1; j > 0; j >>= 1) {
            if (j >= 32) {
                const int a = min(v0, v1), b2 = max(v0, v1);
                v0 = a; v1 = b2;
            } else {
                cmpex(v0, lane,      j, k, lane);
                cmpex(v1, 32 + lane, j, k, lane);
            }
        }
    }
}

__device__ __forceinline__ void bitonic128(int& v0, int& v1, int& v2, int& v3, int lane)
{
    #pragma unroll
    for (int k = 2; k <= 128; k <<= 1) {
        #pragma unroll
        for (int j = k >> 1; j > 0; j >>= 1) {
            if (j == 64) {
                int a, b2;
                a = min(v0, v2); b2 = max(v0, v2); v0 = a; v2 = b2;
                a = min(v1, v3); b2 = max(v1, v3); v1 = a; v3 = b2;
            } else if (j == 32) {
                const bool upA = (((lane)      & k) == 0);
                const bool upB = (((64 + lane) & k) == 0);
                int a, b2;
                a = min(v0, v1); b2 = max(v0, v1);
                v0 = upA ? a : b2;  v1 = upA ? b2 : a;
                a = min(v2, v3); b2 = max(v2, v3);
                v2 = upB ? a : b2;  v3 = upB ? b2 : a;
            } else {
                cmpex(v0, lane,      j, k, lane);
                cmpex(v1, 32 + lane, j, k, lane);
                cmpex(v2, 64 + lane, j, k, lane);
                cmpex(v3, 96 + lane, j, k, lane);
            }
        }
    }
}

// ---------------------------------------------------------------------------
// K4: FUSED ballquery (blocks 0..NBQBLK-1) + transpose (rest).
// Byte-identical to passing R14 (d2 bit-exact vs reference).
// ---------------------------------------------------------------------------
union SmemK4 {
    struct { float s[64][65]; float sxyz[3][64]; } t;
    struct { int hlist[8][HCAP]; int sstart[8][MAXCOL]; int soff[8][MAXCOL + 1]; } q;
};

__global__ void __launch_bounds__(256) fused_bq_transpose_kernel(
    const float* __restrict__ xyz, const float* __restrict__ feat,
    const float* __restrict__ new_xyz)
{
    __shared__ SmemK4 sm;
    const int tid = threadIdx.x;

    if (blockIdx.x < NBQBLK) {
        // ================= ball query =================
        const int bqid = blockIdx.x;
        const int b    = bqid >> 8;
        const int warp = tid >> 5;
        const int lane = tid & 31;
        const int m    = (bqid & 255) * 8 + warp;
        const int q    = b * MM + m;

        const float qx = new_xyz[(b * 3 + 0) * MM + m];
        const float qy = new_xyz[(b * 3 + 1) * MM + m];
        const float qz = new_xyz[(b * 3 + 2) * MM + m];
        const float sq = __fadd_rn(__fadd_rn(__fmul_rn(qx, qx), __fmul_rn(qy, qy)),
                                   __fmul_rn(qz, qz));

        const int xlo = max(0, (int)floorf((qx - RREACH) * 10.0f));
        const int xhi = min(9, (int)floorf((qx + RREACH) * 10.0f));
        const int ylo = max(0, (int)floorf((qy - RREACH) * 10.0f));
        const int yhi = min(9, (int)floorf((qy + RREACH) * 10.0f));
        const int zlo = max(0, (int)floorf((qz - RREACH) * (float)NZC));
        const int zhi = min(NZC - 1, (int)floorf((qz + RREACH) * (float)NZC));

        const int ynum = yhi - ylo + 1;
        const int ncol = (xhi - xlo + 1) * ynum;

        int sc = 0, len = 0;
        if (lane < ncol) {
            const int cx = xlo + lane / ynum;
            const int cy = ylo + (lane - (lane / ynum) * ynum);
            const int base = b * (NCELL + 1) + (cx * 10 + cy) * NZC;
            sc  = g_cellstart[base + zlo];
            len = g_cellstart[base + zhi + 1] - sc;
        }
        int inc = len;
        #pragma unroll
        for (int d = 1; d < 32; d <<= 1) {
            const int t = __shfl_up_sync(0xffffffffu, inc, d);
            if (lane >= d) inc += t;
        }
        const int total = __shfl_sync(0xffffffffu, inc, 31);
        if (lane < ncol) {
            sm.q.sstart[warp][lane] = sc;
            sm.q.soff[warp][lane]   = inc - len;
        }
        if (lane == 0) sm.q.soff[warp][ncol] = total;
        __syncwarp();

        const unsigned lt_mask = (lane == 0) ? 0u : (0xffffffffu >> (32 - lane));
        int cnt = 0;
        int cur = 0;

        for (int p0 = 0; p0 < total; p0 += 32) {
            const int pos = p0 + lane;
            const bool valid = pos < total;
            bool in = false;
            int  pidx = 0;
            if (valid) {
                while (pos >= sm.q.soff[warp][cur + 1]) ++cur;
                const int src = sm.q.sstart[warp][cur] + (pos - sm.q.soff[warp][cur]);
                const float4 p = g_cellpts[b * NN + src];
                const float sp = __fadd_rn(
                    __fadd_rn(__fmul_rn(p.x, p.x), __fmul_rn(p.y, p.y)),
                    __fmul_rn(p.z, p.z));
                float dt = __fmul_rn(qx, p.x);
                dt = __fmaf_rn(qy, p.y, dt);
                dt = __fmaf_rn(qz, p.z, dt);
                const float d2 = __fsub_rn(__fadd_rn(sq, sp), __fmul_rn(2.0f, dt));
                in = d2 < R2;
                pidx = __float_as_int(p.w);
            }
            const unsigned mask = __ballot_sync(0xffffffffu, in);
            if (in) {
                const int posw = cnt + __popc(mask & lt_mask);
                if (posw < HCAP) sm.q.hlist[warp][posw] = pidx;
            }
            cnt += __popc(mask);
        }
        if (cnt > HCAP) cnt = HCAP;

        int v0 = (lane < cnt)      ? sm.q.hlist[warp][lane]      : INT_MAX;
        int v1 = (32 + lane < cnt) ? sm.q.hlist[warp][32 + lane] : INT_MAX;
        if (cnt <= 64) {
            bitonic64(v0, v1, lane);
        } else {
            int v2 = (64 + lane < cnt) ? sm.q.hlist[warp][64 + lane] : INT_MAX;
            int v3 = (96 + lane < cnt) ? sm.q.hlist[warp][96 + lane] : INT_MAX;
            bitonic128(v0, v1, v2, v3, lane);
        }

        const int f0 = __shfl_sync(0xffffffffu, v0, 0);
        const int first = (cnt == 0) ? 0 : f0;
        g_idx[q * 64 + lane]      = (lane < cnt)      ? v0 : first;
        g_idx[q * 64 + 32 + lane] = (32 + lane < cnt) ? v1 : first;
    } else {
        // ================= transpose =================
        const int t_id = blockIdx.x - NBQBLK;
        const int b    = t_id >> 7;
        const int n0   = (t_id & 127) * 64;
        const int p    = tid & 63;
        const int c0   = tid >> 6;

        #pragma unroll
        for (int cc = 0; cc < 64; cc += 4) {
            const int c = cc + c0;
            sm.t.s[c][p] = feat[((size_t)(b * 64 + c)) * NN + n0 + p];
        }
        if (tid < 192) {
            const int c  = tid >> 6;
            const int pp = tid & 63;
            sm.t.sxyz[c][pp] = xyz[((size_t)(b * 3 + c)) * NN + n0 + pp];
        }
        __syncthreads();

        for (int f = tid; f < 64 * 16; f += 256) {
            const int pp = f >> 4;
            const int j  = f & 15;
            const int c  = 4 * j;
            float4 v;
            v.x = sm.t.s[c][pp];     v.y = sm.t.s[c + 1][pp];
            v.z = sm.t.s[c + 2][pp]; v.w = sm.t.s[c + 3][pp];
            ((float4*)(g_feat + (((size_t)(b * NN + n0 + pp)) << 6)))[j] = v;
        }
        if (tid < 64)
            g_xyzw[b * NN + n0 + tid] =
                make_float4(sm.t.sxyz[0][tid], sm.t.sxyz[1][tid],
                            sm.t.sxyz[2][tid], 0.0f);
    }
}

// ---------------------------------------------------------------------------
// Gather + concat with spatially sorted query order (g_qorder).
// FIX vs R15/R16 crash: srow is float4-accessed but shared float arrays only
// get 4B natural alignment; the added 4B s_m shifted srow to offset 260 and
// misaligned every STS.128. srow now carries __align__(16), and the scalar
// lives after the arrays.
// ---------------------------------------------------------------------------
__global__ void __launch_bounds__(256) gather_kernel(
    const float* __restrict__ new_xyz, float* __restrict__ out)
{
    __shared__ __align__(16) float srow[64][64];
    __shared__ float4 sxyz4[64];
    __shared__ int    sidx[64];
    __shared__ int    s_m;
    const int b   = blockIdx.y;
    const int tid = threadIdx.x;

    if (tid == 0) s_m = g_qorder[b * MM + blockIdx.x];
    __syncthreads();
    const int m = s_m;
    const int q = b * MM + m;

    if (tid < 64) sidx[tid] = g_idx[q * 64 + tid];
    __syncthreads();

    if (tid < 64) sxyz4[tid] = g_xyzw[b * NN + sidx[tid]];

    // stage features: 64 rows x 16 quads; each warp-instr covers 2 whole rows
    for (int f = tid; f < 64 * 16; f += 256) {
        const int r = f >> 4;
        const int j = f & 15;
        float4 v = ((const float4*)(g_feat +
                    (((size_t)(b * NN + sidx[r])) << 6)))[j];
        if (r & 1) { float t = v.x; v.x = v.y; v.y = t;
                     t = v.z; v.z = v.w; v.w = t; }
        if (r & 2) { float t = v.x; v.x = v.z; v.z = t;
                     t = v.y; v.y = v.w; v.w = t; }
        const int jq = j ^ ((r >> 2) & 7);
        *((float4*)&srow[r][4 * jq]) = v;
    }
    __syncthreads();

    const float* sxyzf = (const float*)sxyz4;

    for (int t = tid; t < 67 * 8; t += 256) {
        const int c   = t >> 3;
        const int k4h = t & 7;
        float sub = 0.0f;
        if (c < 3) sub = new_xyz[(b * 3 + c) * MM + m];
        #pragma unroll
        for (int h = 0; h < 2; ++h) {
            const int k4 = k4h + 8 * h;
            const int k  = 4 * k4;
            float4 v;
            if (c < 3) {
                v.x = sxyzf[4 * (k + 0) + c] - sub;
                v.y = sxyzf[4 * (k + 1) + c] - sub;
                v.z = sxyzf[4 * (k + 2) + c] - sub;
                v.w = sxyzf[4 * (k + 3) + c] - sub;
            } else {
                const int cf = c - 3;
                v.x = srow[k + 0][cf ^ ((k + 0) & 31)];
                v.y = srow[k + 1][cf ^ ((k + 1) & 31)];
                v.z = srow[k + 2][cf ^ ((k + 2) & 31)];
                v.w = srow[k + 3][cf ^ ((k + 3) & 31)];
            }
            __stcs(((float4*)(out + (((size_t)b * 67 + c) * MM + m) * 64)) + k4, v);
        }
    }
}

// ---------------------------------------------------------------------------
extern "C" void kernel_launch(void* const* d_in, const int* in_sizes, int n_in,
                              void* d_out, int out_size)
{
    const float* new_xyz = (const float*)d_in[0];  // (8, 3, 2048)
    const float* xyz     = (const float*)d_in[1];  // (8, 3, 8192)
    const float* feature = (const float*)d_in[2];  // (8, 64, 8192)
    float* out = (float*)d_out;                    // (8, 67, 2048, 64)

    hist_kernel<<<dim3(NN / 256, BB), 256>>>(xyz);
    qsort_kernel<<<BB, 1024>>>(new_xyz);
    scan_kernel<<<BB, 1024>>>();
    scatter_kernel<<<dim3(NN / 1024, BB), 1024>>>(xyz);
    fused_bq_transpose_kernel<<<NBQBLK + NTRBLK, 256>>>(xyz, feature, new_xyz);
    gather_kernel<<<dim3(MM, BB), 256>>>(new_xyz, out);
}